// round 13
// baseline (speedup 1.0000x reference)
#include <cuda_runtime.h>
#include <cstdint>
#include <math.h>

// Problem constants
#define CB 2
#define CS 2048
#define CD 1024
#define CH 16
#define CDK 64
#define CM (CB*CS)   // 4096 rows

// Scratch (device globals: allocation-free rule)
__device__ float g_q[CB*CS*CD];
__device__ float g_k[CB*CS*CD];
__device__ float g_v[CB*CS*CD];
__device__ float g_a[CB*CS*CD];

// ---------------------------------------------------------------------------
// Helpers
// ---------------------------------------------------------------------------
__device__ __forceinline__ uint32_t smem_u32(const void* p) {
    uint32_t a;
    asm("{ .reg .u64 t; cvta.to.shared.u64 t, %1; cvt.u32.u64 %0, t; }" : "=r"(a) : "l"(p));
    return a;
}
__device__ __forceinline__ void cp_async16(uint32_t dst, const void* src) {
    asm volatile("cp.async.cg.shared.global [%0], [%1], 16;" :: "r"(dst), "l"(src) : "memory");
}
#define CP_COMMIT() asm volatile("cp.async.commit_group;" ::: "memory")
#define CP_WAIT(n)  asm volatile("cp.async.wait_group %0;" :: "n"(n) : "memory")

__device__ __forceinline__ uint32_t f2tf32(float x) {
    uint32_t o;
    asm("cvt.rna.tf32.f32 %0, %1;" : "=r"(o) : "f"(x));
    return o;
}
__device__ __forceinline__ void mma_tf32(float c[4], const uint32_t a[4], const uint32_t b[2]) {
    asm volatile("mma.sync.aligned.m16n8k8.row.col.f32.tf32.tf32.f32 "
                 "{%0,%1,%2,%3}, {%4,%5,%6,%7}, {%8,%9}, {%0,%1,%2,%3};"
                 : "+f"(c[0]), "+f"(c[1]), "+f"(c[2]), "+f"(c[3])
                 : "r"(a[0]), "r"(a[1]), "r"(a[2]), "r"(a[3]), "r"(b[0]), "r"(b[1]));
}
__device__ __forceinline__ void ldsm_x4(uint32_t& r0, uint32_t& r1,
                                        uint32_t& r2, uint32_t& r3, uint32_t a) {
    asm volatile("ldmatrix.sync.aligned.m8n8.x4.shared.b16 {%0,%1,%2,%3}, [%4];"
                 : "=r"(r0), "=r"(r1), "=r"(r2), "=r"(r3) : "r"(a));
}

// Single dynamic smem symbol shared by both kernels.
extern __shared__ char dynsmem[];

// ---------------------------------------------------------------------------
// TF32 tensor-core GEMM v6: C[M,N] = A[M,K] * B[N,K]^T  (fp32 in/out)
// CTA tile 128x128, BK=32, 256 threads (8 warps = 2Mx4N, 64x32 warp tiles).
// 2-stage cp.async, 73.7KB smem -> 2 CTAs/SM (16 warps: cross-CTA latency
// hiding over the per-chunk barriers). Grid (8, 32) = 256 CTAs, single wave
// at occupancy 2. ldmatrix fragments, RNA tf32 cvt.
// ---------------------------------------------------------------------------
#define BM 128
#define BN 128
#define BK 32
#define KST2 36                  // 32 + 4 pad -> conflict-free ldsm rows
#define AW (BM * KST2)           // 4608 words per A stage
#define BW (BN * KST2)           // 4608 words per B stage
#define STGW (AW + BW)           // 9216 words per stage
#define GSMEM6 (2 * STGW * 4)    // 73728 bytes

__global__ void __launch_bounds__(256, 2) gemm_tc(const float* __restrict__ A,
                                                  const float* __restrict__ B,
                                                  float* __restrict__ C,
                                                  int M, int N, int K)
{
    const int tid  = threadIdx.x;
    const int wid  = tid >> 5;
    const int lane = tid & 31;
    const int g    = lane >> 2;
    const int t    = lane & 3;
    const int wm   = wid >> 2;    // 0..1  (64-row slice)
    const int wn   = wid & 3;     // 0..3  (32-col slice)
    const int row0 = blockIdx.y * BM;
    const int col0 = blockIdx.x * BN;

    const int al_row = ((lane >> 3) & 1) * 8 + (lane & 7);
    const int al_col = ((lane >> 4) & 1) * 4;
    const int bl_row = ((lane >> 4) & 1) * 8 + (lane & 7);
    const int bl_col = ((lane >> 3) & 1) * 4;

    const float* Ab = A + (size_t)row0 * K;
    const float* Bb = B + (size_t)col0 * K;

    float acc[4][4][4];
    #pragma unroll
    for (int i = 0; i < 4; i++)
        #pragma unroll
        for (int j = 0; j < 4; j++)
            #pragma unroll
            for (int r = 0; r < 4; r++) acc[i][j][r] = 0.f;

    const int lr8 = tid >> 3;         // 0..31
    const int lc8 = (tid & 7) * 4;    // 0,4,...,28
    const uint32_t s0 = smem_u32(dynsmem);

    auto load_tile = [&](int kc, int s) {
        const float* ag = Ab + kc * BK;
        const float* bg = Bb + kc * BK;
        const uint32_t abase = s0 + s * (STGW * 4);
        const uint32_t bbase = abase + AW * 4;
        #pragma unroll
        for (int i = 0; i < 4; i++) {
            const int r = lr8 + i * 32;
            cp_async16(abase + (r * KST2 + lc8) * 4, ag + (size_t)r * K + lc8);
            cp_async16(bbase + (r * KST2 + lc8) * 4, bg + (size_t)r * K + lc8);
        }
        CP_COMMIT();
    };

    const int NCH = K / BK;   // 32
    load_tile(0, 0);
    int buf = 0;

    for (int kc = 0; kc < NCH; kc++) {
        if (kc + 1 < NCH) {
            load_tile(kc + 1, buf ^ 1);
            CP_WAIT(1);
        } else {
            CP_WAIT(0);
        }
        __syncthreads();

        const uint32_t Ac = s0 + buf * (STGW * 4);
        const uint32_t Bc = Ac + AW * 4;

        #pragma unroll
        for (int ks = 0; ks < 4; ks++) {
            const int kb = ks * 8;
            uint32_t af[4][4], bf[4][2];
            const uint32_t aa = Ac + ((wm * 64 + al_row) * KST2 + kb + al_col) * 4;
            #pragma unroll
            for (int i = 0; i < 4; i++) {
                uint32_t r0, r1, r2, r3;
                ldsm_x4(r0, r1, r2, r3, aa + i * (16 * KST2 * 4));
                af[i][0] = f2tf32(__uint_as_float(r0));
                af[i][1] = f2tf32(__uint_as_float(r1));
                af[i][2] = f2tf32(__uint_as_float(r2));
                af[i][3] = f2tf32(__uint_as_float(r3));
            }
            const uint32_t ba = Bc + ((wn * 32 + bl_row) * KST2 + kb + bl_col) * 4;
            #pragma unroll
            for (int jp = 0; jp < 2; jp++) {
                uint32_t r0, r1, r2, r3;
                ldsm_x4(r0, r1, r2, r3, ba + jp * (16 * KST2 * 4));
                bf[2 * jp][0]     = f2tf32(__uint_as_float(r0));
                bf[2 * jp][1]     = f2tf32(__uint_as_float(r1));
                bf[2 * jp + 1][0] = f2tf32(__uint_as_float(r2));
                bf[2 * jp + 1][1] = f2tf32(__uint_as_float(r3));
            }
            #pragma unroll
            for (int i = 0; i < 4; i++)
                #pragma unroll
                for (int j = 0; j < 4; j++)
                    mma_tf32(acc[i][j], af[i], bf[j]);
        }
        __syncthreads();
        buf ^= 1;
    }

    #pragma unroll
    for (int i = 0; i < 4; i++) {
        #pragma unroll
        for (int j = 0; j < 4; j++) {
            const int m = row0 + wm * 64 + i * 16 + g;
            const int n = col0 + wn * 32 + j * 8 + 2 * t;
            *(float2*)&C[(size_t)m * N + n]       = make_float2(acc[i][j][0], acc[i][j][1]);
            *(float2*)&C[(size_t)(m + 8) * N + n] = make_float2(acc[i][j][2], acc[i][j][3]);
        }
    }
}

// ---------------------------------------------------------------------------
// Tensor-core causal flash attention v6 (tf32 mma.sync) — unchanged from R12.
// 64q/CTA, Q in regs (exp2-domain pre-scale), K double-buffered 64-key
// stages, V single-buffered, 3 CTAs/SM. K/P via ldmatrix, V scalar LDS.
// ---------------------------------------------------------------------------
#define KST 68
#define VST 72
#define PST 68
#define KT  64   // keys per stage
#define QT  64   // queries per CTA

#define OFF_K 0
#define OFF_V (OFF_K + 2 * KT * KST)      // 8704
#define OFF_P (OFF_V + KT * VST)          // 13312
#define AWORDS (OFF_P + QT * PST)         // 17664
#define ASMEM (AWORDS * 4)                // 70656 bytes

__global__ void __launch_bounds__(128, 3) attn_tc(const float* __restrict__ qg,
                                                  const float* __restrict__ kg,
                                                  const float* __restrict__ vg,
                                                  float* __restrict__ og)
{
    uint32_t* smw = (uint32_t*)dynsmem;
    uint32_t* Vsm = smw + OFF_V;
    uint32_t* Ps  = smw + OFF_P;

    const int bh = blockIdx.y;
    const int b  = bh >> 4;
    const int h  = bh & 15;
    const int q0 = (gridDim.x - 1 - blockIdx.x) * QT;   // longest CTAs first
    const int tid = threadIdx.x;
    const int w = tid >> 5, lane = tid & 31;
    const int g = lane >> 2, t = lane & 3;

    const int al_row = ((lane >> 3) & 1) * 8 + (lane & 7);
    const int al_col = ((lane >> 4) & 1) * 4;
    const int bl_row = ((lane >> 4) & 1) * 8 + (lane & 7);
    const int bl_col = ((lane >> 3) & 1) * 4;

    const float* kbase = kg + ((size_t)(b * CS)) * CD + h * CDK;
    const float* vbase = vg + ((size_t)(b * CS)) * CD + h * CDK;

    // Q fragments in registers, pre-scaled by log2(e)/sqrt(64) -> exp2 domain.
    const float QSCALE = 0.125f * 1.4426950408889634f;
    const float* qbase = qg + ((size_t)(b * CS + q0)) * CD + h * CDK;
    uint32_t qf[8][4];
    {
        const float* qr0 = qbase + (size_t)(16 * w + g) * CD;
        const float* qr1 = qbase + (size_t)(16 * w + g + 8) * CD;
        #pragma unroll
        for (int kc = 0; kc < 8; kc++) {
            qf[kc][0] = f2tf32(qr0[8 * kc + t] * QSCALE);
            qf[kc][1] = f2tf32(qr1[8 * kc + t] * QSCALE);
            qf[kc][2] = f2tf32(qr0[8 * kc + t + 4] * QSCALE);
            qf[kc][3] = f2tf32(qr1[8 * kc + t + 4] * QSCALE);
        }
    }

    const uint32_t kb0 = smem_u32(smw);
    const uint32_t vb0 = smem_u32(Vsm);
    const uint32_t pb0 = smem_u32(Ps);

    auto load_K = [&](int kt_, int s) {
        const int k0 = kt_ * KT;
        const uint32_t kd = kb0 + s * (KT * KST * 4);
        #pragma unroll
        for (int i = 0; i < 8; i++) {
            int idx = tid + i * 128;
            int r = idx >> 4, c = idx & 15;
            cp_async16(kd + r * (KST * 4) + c * 16, kbase + (size_t)(k0 + r) * CD + c * 4);
        }
        CP_COMMIT();
    };
    auto load_V = [&](int kt_) {
        const int k0 = kt_ * KT;
        #pragma unroll
        for (int i = 0; i < 8; i++) {
            int idx = tid + i * 128;
            int r = idx >> 4, c = idx & 15;
            cp_async16(vb0 + r * (VST * 4) + c * 16, vbase + (size_t)(k0 + r) * CD + c * 4);
        }
        CP_COMMIT();
    };

    float o[8][4];
    #pragma unroll
    for (int nt = 0; nt < 8; nt++)
        #pragma unroll
        for (int c = 0; c < 4; c++) o[nt][c] = 0.f;
    float mrow[2] = {-1e30f, -1e30f};
    float lrow[2] = {0.f, 0.f};

    const int ntiles = q0 / KT + 1;
    int buf = 0;
    load_K(0, 0);
    load_V(0);

    for (int kt = 0; kt < ntiles; kt++) {
        const int k0 = kt * KT;
        if (kt + 1 < ntiles) {
            load_K(kt + 1, buf ^ 1);
            CP_WAIT(1);            // K(kt) and V(kt) complete
        } else {
            CP_WAIT(0);
        }
        __syncthreads();

        if (k0 <= q0 + 16 * w + 15) {
            const uint32_t Kb = kb0 + buf * (KT * KST * 4);

            // S = Q * K^T  (K fragments via ldmatrix; raw fp32 -> HW tf32)
            float s[8][4];
            #pragma unroll
            for (int nt = 0; nt < 8; nt++)
                #pragma unroll
                for (int c = 0; c < 4; c++) s[nt][c] = 0.f;

            #pragma unroll
            for (int kc = 0; kc < 8; kc++) {
                uint32_t bf[8][2];
                const uint32_t ka = Kb + (bl_row * KST + 8 * kc + bl_col) * 4;
                #pragma unroll
                for (int p_ = 0; p_ < 4; p_++)
                    ldsm_x4(bf[2 * p_][0], bf[2 * p_][1],
                            bf[2 * p_ + 1][0], bf[2 * p_ + 1][1],
                            ka + p_ * (16 * KST * 4));
                #pragma unroll
                for (int nt = 0; nt < 8; nt++)
                    mma_tf32(s[nt], qf[kc], bf[nt]);
            }

            // causal mask (diagonal tiles only; scale folded into Q)
            const bool needmask = (k0 + KT - 1) > (q0 + 16 * w);
            if (needmask) {
                #pragma unroll
                for (int nt = 0; nt < 8; nt++)
                    #pragma unroll
                    for (int c = 0; c < 4; c++) {
                        int key = k0 + 8 * nt + 2 * t + (c & 1);
                        int qr  = q0 + 16 * w + 8 * (c >> 1) + g;
                        if (key > qr) s[nt][c] = -1e30f;
                    }
            }

            // online softmax in exp2 domain (row pair p=0,1 across the quad)
            #pragma unroll
            for (int p = 0; p < 2; p++) {
                float mx = -1e30f;
                #pragma unroll
                for (int nt = 0; nt < 8; nt++) {
                    mx = fmaxf(mx, s[nt][2 * p]);
                    mx = fmaxf(mx, s[nt][2 * p + 1]);
                }
                mx = fmaxf(mx, __shfl_xor_sync(0xffffffffu, mx, 1));
                mx = fmaxf(mx, __shfl_xor_sync(0xffffffffu, mx, 2));
                const float mnew = fmaxf(mrow[p], mx);
                const float corr = exp2f(mrow[p] - mnew);
                mrow[p] = mnew;
                float ls = 0.f;
                #pragma unroll
                for (int nt = 0; nt < 8; nt++) {
                    float p0 = exp2f(s[nt][2 * p]     - mnew);
                    float p1 = exp2f(s[nt][2 * p + 1] - mnew);
                    s[nt][2 * p]     = p0;
                    s[nt][2 * p + 1] = p1;
                    ls += p0 + p1;
                }
                #pragma unroll
                for (int nt = 0; nt < 8; nt++) {
                    o[nt][2 * p]     *= corr;
                    o[nt][2 * p + 1] *= corr;
                }
                lrow[p] = lrow[p] * corr + ls;
            }

            // P -> smem (C-frag -> A-frag layout), RNA tf32
            #pragma unroll
            for (int p = 0; p < 2; p++) {
                const int row = 16 * w + 8 * p + g;
                #pragma unroll
                for (int nt = 0; nt < 8; nt++) {
                    uint2 pv = make_uint2(f2tf32(s[nt][2 * p]),
                                          f2tf32(s[nt][2 * p + 1]));
                    *(uint2*)&Ps[row * PST + 8 * nt + 2 * t] = pv;
                }
            }
            __syncwarp();

            // O += P * V  (P via ldmatrix, V transposed scalar LDS)
            #pragma unroll
            for (int kc = 0; kc < 8; kc++) {
                uint32_t af[4];
                ldsm_x4(af[0], af[1], af[2], af[3],
                        pb0 + ((16 * w + al_row) * PST + 8 * kc + al_col) * 4);
                #pragma unroll
                for (int nt = 0; nt < 8; nt++) {
                    uint32_t bf[2];
                    bf[0] = Vsm[(8 * kc + t)     * VST + 8 * nt + g];
                    bf[1] = Vsm[(8 * kc + t + 4) * VST + 8 * nt + g];
                    mma_tf32(o[nt], af, bf);
                }
            }
        }
        __syncthreads();           // all warps done with V(kt)
        if (kt + 1 < ntiles) load_V(kt + 1);
        buf ^= 1;
    }

    // finalize
    float inv[2];
    #pragma unroll
    for (int p = 0; p < 2; p++) {
        float lr = lrow[p];
        lr += __shfl_xor_sync(0xffffffffu, lr, 1);
        lr += __shfl_xor_sync(0xffffffffu, lr, 2);
        inv[p] = 1.f / lr;
    }

    float* obase = og + ((size_t)(b * CS + q0)) * CD + h * CDK;
    #pragma unroll
    for (int nt = 0; nt < 8; nt++) {
        const int r0 = 16 * w + g;
        *(float2*)(obase + (size_t)r0 * CD + 8 * nt + 2 * t) =
            make_float2(o[nt][0] * inv[0], o[nt][1] * inv[0]);
        *(float2*)(obase + (size_t)(r0 + 8) * CD + 8 * nt + 2 * t) =
            make_float2(o[nt][2] * inv[1], o[nt][3] * inv[1]);
    }
}

// ---------------------------------------------------------------------------
// Launch. Inputs: Q, K, V, mask(ignored), w_q, w_k, w_v, w_o. Out: [B,S,D] f32
// ---------------------------------------------------------------------------
extern "C" void kernel_launch(void* const* d_in, const int* in_sizes, int n_in,
                              void* d_out, int out_size)
{
    const float* Q  = (const float*)d_in[0];
    const float* K  = (const float*)d_in[1];
    const float* V  = (const float*)d_in[2];
    const float* wq = (const float*)d_in[4];
    const float* wk = (const float*)d_in[5];
    const float* wv = (const float*)d_in[6];
    const float* wo = (const float*)d_in[7];
    float* out = (float*)d_out;

    float *qb, *kb, *vb, *ab;
    cudaGetSymbolAddress((void**)&qb, g_q);
    cudaGetSymbolAddress((void**)&kb, g_k);
    cudaGetSymbolAddress((void**)&vb, g_v);
    cudaGetSymbolAddress((void**)&ab, g_a);

    cudaFuncSetAttribute(gemm_tc, cudaFuncAttributeMaxDynamicSharedMemorySize, GSMEM6);
    cudaFuncSetAttribute(attn_tc, cudaFuncAttributeMaxDynamicSharedMemorySize, ASMEM);

    dim3 gg(CD / BN, CM / BM);   // (8, 32) = 256 CTAs, single wave at occ 2
    gemm_tc<<<gg, 256, GSMEM6>>>(Q, wq, qb, CM, CD, CD);
    gemm_tc<<<gg, 256, GSMEM6>>>(K, wk, kb, CM, CD, CD);
    gemm_tc<<<gg, 256, GSMEM6>>>(V, wv, vb, CM, CD, CD);

    attn_tc<<<dim3(CS / QT, CB * CH), 128, ASMEM>>>(qb, kb, vb, ab);

    gemm_tc<<<gg, 256, GSMEM6>>>(ab, wo, out, CM, CD, CD);
}

// round 14
// speedup vs baseline: 1.0201x; 1.0201x over previous
#include <cuda_runtime.h>
#include <cstdint>
#include <math.h>

// Problem constants
#define CB 2
#define CS 2048
#define CD 1024
#define CH 16
#define CDK 64
#define CM (CB*CS)   // 4096 rows

// Scratch (device globals: allocation-free rule)
__device__ float g_q[CB*CS*CD];
__device__ float g_k[CB*CS*CD];
__device__ float g_v[CB*CS*CD];   // holds Vt: [h*64+d][b*2048+s]
__device__ float g_a[CB*CS*CD];

// ---------------------------------------------------------------------------
// Helpers
// ---------------------------------------------------------------------------
__device__ __forceinline__ uint32_t smem_u32(const void* p) {
    uint32_t a;
    asm("{ .reg .u64 t; cvta.to.shared.u64 t, %1; cvt.u32.u64 %0, t; }" : "=r"(a) : "l"(p));
    return a;
}
__device__ __forceinline__ void cp_async16(uint32_t dst, const void* src) {
    asm volatile("cp.async.cg.shared.global [%0], [%1], 16;" :: "r"(dst), "l"(src) : "memory");
}
#define CP_COMMIT() asm volatile("cp.async.commit_group;" ::: "memory")
#define CP_WAIT(n)  asm volatile("cp.async.wait_group %0;" :: "n"(n) : "memory")

__device__ __forceinline__ uint32_t f2tf32(float x) {
    uint32_t o;
    asm("cvt.rna.tf32.f32 %0, %1;" : "=r"(o) : "f"(x));
    return o;
}
__device__ __forceinline__ void mma_tf32(float c[4], const uint32_t a[4], const uint32_t b[2]) {
    asm volatile("mma.sync.aligned.m16n8k8.row.col.f32.tf32.tf32.f32 "
                 "{%0,%1,%2,%3}, {%4,%5,%6,%7}, {%8,%9}, {%0,%1,%2,%3};"
                 : "+f"(c[0]), "+f"(c[1]), "+f"(c[2]), "+f"(c[3])
                 : "r"(a[0]), "r"(a[1]), "r"(a[2]), "r"(a[3]), "r"(b[0]), "r"(b[1]));
}
__device__ __forceinline__ void ldsm_x4(uint32_t& r0, uint32_t& r1,
                                        uint32_t& r2, uint32_t& r3, uint32_t a) {
    asm volatile("ldmatrix.sync.aligned.m8n8.x4.shared.b16 {%0,%1,%2,%3}, [%4];"
                 : "=r"(r0), "=r"(r1), "=r"(r2), "=r"(r3) : "r"(a));
}

// Single dynamic smem symbol shared by both kernels.
extern __shared__ char dynsmem[];

// ---------------------------------------------------------------------------
// TF32 tensor-core GEMM (R12 config = measured best): C = A[M,K]*B[N,K]^T.
// CTA tile 128x256, BK=32, 256 threads (8 warps 2Mx4N, 64x64 warp tiles),
// 2-stage cp.async with decoupled prefetch. Grid (4,32)=128 CTAs, 1 wave.
// TRANS=1: store C transposed (C_t[n*M + m]) — used for the V projection.
// ---------------------------------------------------------------------------
#define BM 128
#define BN 256
#define BK 32
#define KST2 36                  // 32 + 4 pad
#define AW (BM * KST2)           // 4608 words per A stage
#define BW (BN * KST2)           // 9216 words per B stage
#define STGW (AW + BW)           // 13824 words per stage
#define GSMEM5 (2 * STGW * 4)    // 110592 bytes

template<int TRANS>
__global__ void __launch_bounds__(256, 1) gemm_tc(const float* __restrict__ A,
                                                  const float* __restrict__ B,
                                                  float* __restrict__ C,
                                                  int M, int N, int K)
{
    const int tid  = threadIdx.x;
    const int wid  = tid >> 5;
    const int lane = tid & 31;
    const int g    = lane >> 2;
    const int t    = lane & 3;
    const int wm   = wid >> 2;    // 0..1
    const int wn   = wid & 3;     // 0..3
    const int row0 = blockIdx.y * BM;
    const int col0 = blockIdx.x * BN;

    const int al_row = ((lane >> 3) & 1) * 8 + (lane & 7);
    const int al_col = ((lane >> 4) & 1) * 4;
    const int bl_row = ((lane >> 4) & 1) * 8 + (lane & 7);
    const int bl_col = ((lane >> 3) & 1) * 4;

    const float* Ab = A + (size_t)row0 * K;
    const float* Bb = B + (size_t)col0 * K;

    float acc[4][8][4];
    #pragma unroll
    for (int i = 0; i < 4; i++)
        #pragma unroll
        for (int j = 0; j < 8; j++)
            #pragma unroll
            for (int r = 0; r < 4; r++) acc[i][j][r] = 0.f;

    const int lr8 = tid >> 3;         // 0..31
    const int lc8 = (tid & 7) * 4;    // 0,4,...,28
    const uint32_t s0 = smem_u32(dynsmem);

    auto load_tile = [&](int kc, int s) {
        const float* ag = Ab + kc * BK;
        const float* bg = Bb + kc * BK;
        const uint32_t abase = s0 + s * (STGW * 4);
        const uint32_t bbase = abase + AW * 4;
        #pragma unroll
        for (int i = 0; i < 4; i++) {
            const int r = lr8 + i * 32;
            cp_async16(abase + (r * KST2 + lc8) * 4, ag + (size_t)r * K + lc8);
        }
        #pragma unroll
        for (int i = 0; i < 8; i++) {
            const int r = lr8 + i * 32;
            cp_async16(bbase + (r * KST2 + lc8) * 4, bg + (size_t)r * K + lc8);
        }
        CP_COMMIT();
    };

    const int NCH = K / BK;   // 32
    load_tile(0, 0);
    int buf = 0;

    for (int kc = 0; kc < NCH; kc++) {
        if (kc + 1 < NCH) {
            load_tile(kc + 1, buf ^ 1);
            CP_WAIT(1);
        } else {
            CP_WAIT(0);
        }
        __syncthreads();

        const uint32_t Ac = s0 + buf * (STGW * 4);
        const uint32_t Bc = Ac + AW * 4;

        #pragma unroll
        for (int ks = 0; ks < 4; ks++) {
            const int kb = ks * 8;
            uint32_t af[4][4], bf[8][2];
            const uint32_t aa = Ac + ((wm * 64 + al_row) * KST2 + kb + al_col) * 4;
            #pragma unroll
            for (int i = 0; i < 4; i++) {
                uint32_t r0, r1, r2, r3;
                ldsm_x4(r0, r1, r2, r3, aa + i * (16 * KST2 * 4));
                af[i][0] = f2tf32(__uint_as_float(r0));
                af[i][1] = f2tf32(__uint_as_float(r1));
                af[i][2] = f2tf32(__uint_as_float(r2));
                af[i][3] = f2tf32(__uint_as_float(r3));
            }
            const uint32_t ba = Bc + ((wn * 64 + bl_row) * KST2 + kb + bl_col) * 4;
            #pragma unroll
            for (int jp = 0; jp < 4; jp++) {
                uint32_t r0, r1, r2, r3;
                ldsm_x4(r0, r1, r2, r3, ba + jp * (16 * KST2 * 4));
                bf[2 * jp][0]     = f2tf32(__uint_as_float(r0));
                bf[2 * jp][1]     = f2tf32(__uint_as_float(r1));
                bf[2 * jp + 1][0] = f2tf32(__uint_as_float(r2));
                bf[2 * jp + 1][1] = f2tf32(__uint_as_float(r3));
            }
            #pragma unroll
            for (int i = 0; i < 4; i++)
                #pragma unroll
                for (int j = 0; j < 8; j++)
                    mma_tf32(acc[i][j], af[i], bf[j]);
        }
        __syncthreads();
        buf ^= 1;
    }

    #pragma unroll
    for (int i = 0; i < 4; i++) {
        #pragma unroll
        for (int j = 0; j < 8; j++) {
            const int m = row0 + wm * 64 + i * 16 + g;
            const int n = col0 + wn * 64 + j * 8 + 2 * t;
            if (TRANS) {
                // C_t[n][m] (head-dim major): scattered fp32 stores
                C[(size_t)n * M + m]           = acc[i][j][0];
                C[(size_t)(n + 1) * M + m]     = acc[i][j][1];
                C[(size_t)n * M + m + 8]       = acc[i][j][2];
                C[(size_t)(n + 1) * M + m + 8] = acc[i][j][3];
            } else {
                *(float2*)&C[(size_t)m * N + n]       = make_float2(acc[i][j][0], acc[i][j][1]);
                *(float2*)&C[(size_t)(m + 8) * N + n] = make_float2(acc[i][j][2], acc[i][j][3]);
            }
        }
    }
}

// ---------------------------------------------------------------------------
// Tensor-core causal flash attention v7 (tf32 mma.sync).
// As v6 (64q/CTA, Q in regs exp2-scaled, K 2-stage, V single-buffered,
// 3 CTAs/SM) but V arrives TRANSPOSED from the V-projection GEMM
// (Vt[d][seq]) so PV B-fragments use ldmatrix like K: per warp-tile the
// 128 scalar V LDS become 32 LDSM.
// ---------------------------------------------------------------------------
#define KST 68
#define VST 68
#define PST 68
#define KT  64   // keys per stage
#define QT  64   // queries per CTA

#define OFF_K 0
#define OFF_V (OFF_K + 2 * KT * KST)      // 8704
#define OFF_P (OFF_V + CDK * VST)         // 13056
#define AWORDS (OFF_P + QT * PST)         // 17408
#define ASMEM (AWORDS * 4)                // 69632 bytes

__global__ void __launch_bounds__(128, 3) attn_tc(const float* __restrict__ qg,
                                                  const float* __restrict__ kg,
                                                  const float* __restrict__ vtg,
                                                  float* __restrict__ og)
{
    uint32_t* smw = (uint32_t*)dynsmem;
    uint32_t* Ps  = smw + OFF_P;

    const int bh = blockIdx.y;
    const int b  = bh >> 4;
    const int h  = bh & 15;
    const int q0 = (gridDim.x - 1 - blockIdx.x) * QT;   // longest CTAs first
    const int tid = threadIdx.x;
    const int w = tid >> 5, lane = tid & 31;
    const int g = lane >> 2, t = lane & 3;

    const int al_row = ((lane >> 3) & 1) * 8 + (lane & 7);
    const int al_col = ((lane >> 4) & 1) * 4;
    const int bl_row = ((lane >> 4) & 1) * 8 + (lane & 7);
    const int bl_col = ((lane >> 3) & 1) * 4;

    const float* kbase  = kg + ((size_t)(b * CS)) * CD + h * CDK;
    // Vt layout: [h*64 + d][b*2048 + s]
    const float* vtbase = vtg + ((size_t)(h * CDK)) * CM + (size_t)b * CS;

    // Q fragments in registers, pre-scaled by log2(e)/sqrt(64) -> exp2 domain.
    const float QSCALE = 0.125f * 1.4426950408889634f;
    const float* qbase = qg + ((size_t)(b * CS + q0)) * CD + h * CDK;
    uint32_t qf[8][4];
    {
        const float* qr0 = qbase + (size_t)(16 * w + g) * CD;
        const float* qr1 = qbase + (size_t)(16 * w + g + 8) * CD;
        #pragma unroll
        for (int kc = 0; kc < 8; kc++) {
            qf[kc][0] = f2tf32(qr0[8 * kc + t] * QSCALE);
            qf[kc][1] = f2tf32(qr1[8 * kc + t] * QSCALE);
            qf[kc][2] = f2tf32(qr0[8 * kc + t + 4] * QSCALE);
            qf[kc][3] = f2tf32(qr1[8 * kc + t + 4] * QSCALE);
        }
    }

    const uint32_t kb0 = smem_u32(smw);
    const uint32_t vb0 = kb0 + OFF_V * 4;
    const uint32_t pb0 = kb0 + OFF_P * 4;

    auto load_K = [&](int kt_, int s) {
        const int k0 = kt_ * KT;
        const uint32_t kd = kb0 + s * (KT * KST * 4);
        #pragma unroll
        for (int i = 0; i < 8; i++) {
            int idx = tid + i * 128;
            int r = idx >> 4, c = idx & 15;
            cp_async16(kd + r * (KST * 4) + c * 16, kbase + (size_t)(k0 + r) * CD + c * 4);
        }
        CP_COMMIT();
    };
    // Vt tile: 64 dim-rows x 64 keys, coalesced along seq
    auto load_V = [&](int kt_) {
        const int k0 = kt_ * KT;
        #pragma unroll
        for (int i = 0; i < 8; i++) {
            int idx = tid + i * 128;
            int r = idx >> 4, c = idx & 15;
            cp_async16(vb0 + r * (VST * 4) + c * 16, vtbase + (size_t)r * CM + k0 + c * 4);
        }
        CP_COMMIT();
    };

    float o[8][4];
    #pragma unroll
    for (int nt = 0; nt < 8; nt++)
        #pragma unroll
        for (int c = 0; c < 4; c++) o[nt][c] = 0.f;
    float mrow[2] = {-1e30f, -1e30f};
    float lrow[2] = {0.f, 0.f};

    const int ntiles = q0 / KT + 1;
    int buf = 0;
    load_K(0, 0);
    load_V(0);

    for (int kt = 0; kt < ntiles; kt++) {
        const int k0 = kt * KT;
        if (kt + 1 < ntiles) {
            load_K(kt + 1, buf ^ 1);
            CP_WAIT(1);            // K(kt) and V(kt) complete
        } else {
            CP_WAIT(0);
        }
        __syncthreads();

        if (k0 <= q0 + 16 * w + 15) {
            const uint32_t Kb = kb0 + buf * (KT * KST * 4);

            // S = Q * K^T  (K fragments via ldmatrix; raw fp32 -> HW tf32)
            float s[8][4];
            #pragma unroll
            for (int nt = 0; nt < 8; nt++)
                #pragma unroll
                for (int c = 0; c < 4; c++) s[nt][c] = 0.f;

            #pragma unroll
            for (int kc = 0; kc < 8; kc++) {
                uint32_t bf[8][2];
                const uint32_t ka = Kb + (bl_row * KST + 8 * kc + bl_col) * 4;
                #pragma unroll
                for (int p_ = 0; p_ < 4; p_++)
                    ldsm_x4(bf[2 * p_][0], bf[2 * p_][1],
                            bf[2 * p_ + 1][0], bf[2 * p_ + 1][1],
                            ka + p_ * (16 * KST * 4));
                #pragma unroll
                for (int nt = 0; nt < 8; nt++)
                    mma_tf32(s[nt], qf[kc], bf[nt]);
            }

            // causal mask (diagonal tiles only; scale folded into Q)
            const bool needmask = (k0 + KT - 1) > (q0 + 16 * w);
            if (needmask) {
                #pragma unroll
                for (int nt = 0; nt < 8; nt++)
                    #pragma unroll
                    for (int c = 0; c < 4; c++) {
                        int key = k0 + 8 * nt + 2 * t + (c & 1);
                        int qr  = q0 + 16 * w + 8 * (c >> 1) + g;
                        if (key > qr) s[nt][c] = -1e30f;
                    }
            }

            // online softmax in exp2 domain (row pair p=0,1 across the quad)
            #pragma unroll
            for (int p = 0; p < 2; p++) {
                float mx = -1e30f;
                #pragma unroll
                for (int nt = 0; nt < 8; nt++) {
                    mx = fmaxf(mx, s[nt][2 * p]);
                    mx = fmaxf(mx, s[nt][2 * p + 1]);
                }
                mx = fmaxf(mx, __shfl_xor_sync(0xffffffffu, mx, 1));
                mx = fmaxf(mx, __shfl_xor_sync(0xffffffffu, mx, 2));
                const float mnew = fmaxf(mrow[p], mx);
                const float corr = exp2f(mrow[p] - mnew);
                mrow[p] = mnew;
                float ls = 0.f;
                #pragma unroll
                for (int nt = 0; nt < 8; nt++) {
                    float p0 = exp2f(s[nt][2 * p]     - mnew);
                    float p1 = exp2f(s[nt][2 * p + 1] - mnew);
                    s[nt][2 * p]     = p0;
                    s[nt][2 * p + 1] = p1;
                    ls += p0 + p1;
                }
                #pragma unroll
                for (int nt = 0; nt < 8; nt++) {
                    o[nt][2 * p]     *= corr;
                    o[nt][2 * p + 1] *= corr;
                }
                lrow[p] = lrow[p] * corr + ls;
            }

            // P -> smem (C-frag -> A-frag layout), RNA tf32
            #pragma unroll
            for (int p = 0; p < 2; p++) {
                const int row = 16 * w + 8 * p + g;
                #pragma unroll
                for (int nt = 0; nt < 8; nt++) {
                    uint2 pv = make_uint2(f2tf32(s[nt][2 * p]),
                                          f2tf32(s[nt][2 * p + 1]));
                    *(uint2*)&Ps[row * PST + 8 * nt + 2 * t] = pv;
                }
            }
            __syncwarp();

            // O += P * V  (P via ldmatrix A-pattern, Vt via ldmatrix B-pattern;
            // Vt rows = output dims, cols = keys -> same pattern as K in QK)
            #pragma unroll
            for (int kc = 0; kc < 8; kc++) {
                uint32_t af[4];
                ldsm_x4(af[0], af[1], af[2], af[3],
                        pb0 + ((16 * w + al_row) * PST + 8 * kc + al_col) * 4);
                uint32_t bf[8][2];
                const uint32_t va = vb0 + (bl_row * VST + 8 * kc + bl_col) * 4;
                #pragma unroll
                for (int p_ = 0; p_ < 4; p_++)
                    ldsm_x4(bf[2 * p_][0], bf[2 * p_][1],
                            bf[2 * p_ + 1][0], bf[2 * p_ + 1][1],
                            va + p_ * (16 * VST * 4));
                #pragma unroll
                for (int nt = 0; nt < 8; nt++)
                    mma_tf32(o[nt], af, bf[nt]);
            }
        }
        __syncthreads();           // all warps done with V(kt)
        if (kt + 1 < ntiles) load_V(kt + 1);
        buf ^= 1;
    }

    // finalize
    float inv[2];
    #pragma unroll
    for (int p = 0; p < 2; p++) {
        float lr = lrow[p];
        lr += __shfl_xor_sync(0xffffffffu, lr, 1);
        lr += __shfl_xor_sync(0xffffffffu, lr, 2);
        inv[p] = 1.f / lr;
    }

    float* obase = og + ((size_t)(b * CS + q0)) * CD + h * CDK;
    #pragma unroll
    for (int nt = 0; nt < 8; nt++) {
        const int r0 = 16 * w + g;
        *(float2*)(obase + (size_t)r0 * CD + 8 * nt + 2 * t) =
            make_float2(o[nt][0] * inv[0], o[nt][1] * inv[0]);
        *(float2*)(obase + (size_t)(r0 + 8) * CD + 8 * nt + 2 * t) =
            make_float2(o[nt][2] * inv[1], o[nt][3] * inv[1]);
    }
}

// ---------------------------------------------------------------------------
// Launch. Inputs: Q, K, V, mask(ignored), w_q, w_k, w_v, w_o. Out: [B,S,D] f32
// ---------------------------------------------------------------------------
extern "C" void kernel_launch(void* const* d_in, const int* in_sizes, int n_in,
                              void* d_out, int out_size)
{
    const float* Q  = (const float*)d_in[0];
    const float* K  = (const float*)d_in[1];
    const float* V  = (const float*)d_in[2];
    const float* wq = (const float*)d_in[4];
    const float* wk = (const float*)d_in[5];
    const float* wv = (const float*)d_in[6];
    const float* wo = (const float*)d_in[7];
    float* out = (float*)d_out;

    float *qb, *kb, *vb, *ab;
    cudaGetSymbolAddress((void**)&qb, g_q);
    cudaGetSymbolAddress((void**)&kb, g_k);
    cudaGetSymbolAddress((void**)&vb, g_v);
    cudaGetSymbolAddress((void**)&ab, g_a);

    cudaFuncSetAttribute(gemm_tc<0>, cudaFuncAttributeMaxDynamicSharedMemorySize, GSMEM5);
    cudaFuncSetAttribute(gemm_tc<1>, cudaFuncAttributeMaxDynamicSharedMemorySize, GSMEM5);
    cudaFuncSetAttribute(attn_tc, cudaFuncAttributeMaxDynamicSharedMemorySize, ASMEM);

    dim3 gg(CD / BN, CM / BM);   // (4, 32) = 128 CTAs, single wave
    gemm_tc<0><<<gg, 256, GSMEM5>>>(Q, wq, qb, CM, CD, CD);
    gemm_tc<0><<<gg, 256, GSMEM5>>>(K, wk, kb, CM, CD, CD);
    gemm_tc<1><<<gg, 256, GSMEM5>>>(V, wv, vb, CM, CD, CD);   // writes Vt

    attn_tc<<<dim3(CS / QT, CB * CH), 128, ASMEM>>>(qb, kb, vb, ab);

    gemm_tc<0><<<gg, 256, GSMEM5>>>(ab, wo, out, CM, CD, CD);
}

// round 15
// speedup vs baseline: 1.7029x; 1.6693x over previous
#include <cuda_runtime.h>
#include <cuda_fp16.h>
#include <cstdint>
#include <math.h>

// Problem constants
#define CB 2
#define CS 2048
#define CD 1024
#define CH 16
#define CDK 64
#define CM (CB*CS)   // 4096 rows

// fp16 scratch (device globals: allocation-free rule). 64MB total.
__device__ __half h_in_q[CB*CS*CD];
__device__ __half h_in_k[CB*CS*CD];
__device__ __half h_in_v[CB*CS*CD];
__device__ __half h_wq[CD*CD];
__device__ __half h_wk[CD*CD];
__device__ __half h_wv[CD*CD];
__device__ __half h_wo[CD*CD];
__device__ __half h_q[CB*CS*CD];
__device__ __half h_k[CB*CS*CD];
__device__ __half h_vt[CB*CS*CD];   // Vt: [h*64+d][b*2048+s]
__device__ __half h_ao[CB*CS*CD];

// ---------------------------------------------------------------------------
// Helpers
// ---------------------------------------------------------------------------
__device__ __forceinline__ uint32_t smem_u32(const void* p) {
    uint32_t a;
    asm("{ .reg .u64 t; cvta.to.shared.u64 t, %1; cvt.u32.u64 %0, t; }" : "=r"(a) : "l"(p));
    return a;
}
__device__ __forceinline__ void cp_async16(uint32_t dst, const void* src) {
    asm volatile("cp.async.cg.shared.global [%0], [%1], 16;" :: "r"(dst), "l"(src) : "memory");
}
#define CP_COMMIT() asm volatile("cp.async.commit_group;" ::: "memory")
#define CP_WAIT(n)  asm volatile("cp.async.wait_group %0;" :: "n"(n) : "memory")

__device__ __forceinline__ void mma_f16(float c[4], const uint32_t a[4], const uint32_t b[2]) {
    asm volatile("mma.sync.aligned.m16n8k16.row.col.f32.f16.f16.f32 "
                 "{%0,%1,%2,%3}, {%4,%5,%6,%7}, {%8,%9}, {%0,%1,%2,%3};"
                 : "+f"(c[0]), "+f"(c[1]), "+f"(c[2]), "+f"(c[3])
                 : "r"(a[0]), "r"(a[1]), "r"(a[2]), "r"(a[3]), "r"(b[0]), "r"(b[1]));
}
__device__ __forceinline__ void ldsm_x4(uint32_t& r0, uint32_t& r1,
                                        uint32_t& r2, uint32_t& r3, uint32_t a) {
    asm volatile("ldmatrix.sync.aligned.m8n8.x4.shared.b16 {%0,%1,%2,%3}, [%4];"
                 : "=r"(r0), "=r"(r1), "=r"(r2), "=r"(r3) : "r"(a));
}
__device__ __forceinline__ uint32_t pack_h2(float x, float y) {
    __half2 h = __floats2half2_rn(x, y);
    return *(uint32_t*)&h;
}

// Single dynamic smem symbol shared by both kernels.
extern __shared__ char dynsmem[];

// ---------------------------------------------------------------------------
// fp32 -> fp16 conversion prepass (vectorized, RN)
// ---------------------------------------------------------------------------
__global__ void __launch_bounds__(256) cvt16(const float* __restrict__ in,
                                             __half* __restrict__ out, int n4)
{
    int i = blockIdx.x * 256 + threadIdx.x;
    if (i < n4) {
        float4 v = ((const float4*)in)[i];
        __half2 h0 = __floats2half2_rn(v.x, v.y);
        __half2 h1 = __floats2half2_rn(v.z, v.w);
        ((__half2*)out)[2 * i]     = h0;
        ((__half2*)out)[2 * i + 1] = h1;
    }
}

// ---------------------------------------------------------------------------
// FP16 tensor-core GEMM: C[M,N] = A[M,K] * B[N,K]^T  (fp16 in, fp32 accum)
// CTA tile 128x256, BK=64 halves, 256 threads (8 warps 2Mx4N, 64x64 warp
// tiles). 2-stage cp.async, decoupled prefetch. Grid (4,32)=128 CTAs.
// MODE 0: fp16 out; MODE 1: fp16 out transposed (C_t[n][m]); MODE 2: fp32 out.
// ---------------------------------------------------------------------------
#define BM 128
#define BN 256
#define BKH 64
#define KSH 72                     // 64 + 8 pad halves; 144B rows (16B-mult)
#define AWB (BM * KSH * 2)         // 18432 B per A stage
#define BWB (BN * KSH * 2)         // 36864 B per B stage
#define STGB (AWB + BWB)           // 55296 B per stage
#define GSMEMH (2 * STGB)          // 110592 B

template<int MODE>
__global__ void __launch_bounds__(256, 1) gemm_h(const __half* __restrict__ A,
                                                 const __half* __restrict__ B,
                                                 void* __restrict__ Cv,
                                                 int M, int N, int K)
{
    const int tid  = threadIdx.x;
    const int wid  = tid >> 5;
    const int lane = tid & 31;
    const int g    = lane >> 2;
    const int t    = lane & 3;
    const int wm   = wid >> 2;    // 0..1
    const int wn   = wid & 3;     // 0..3
    const int row0 = blockIdx.y * BM;
    const int col0 = blockIdx.x * BN;

    // ldmatrix lane maps (halves)
    const int al_row = ((lane >> 3) & 1) * 8 + (lane & 7);
    const int al_col = ((lane >> 4) & 1) * 8;
    const int bl_row = ((lane >> 4) & 1) * 8 + (lane & 7);
    const int bl_col = ((lane >> 3) & 1) * 8;

    const __half* Ab = A + (size_t)row0 * K;
    const __half* Bb = B + (size_t)col0 * K;

    float acc[4][8][4];
    #pragma unroll
    for (int i = 0; i < 4; i++)
        #pragma unroll
        for (int j = 0; j < 8; j++)
            #pragma unroll
            for (int r = 0; r < 4; r++) acc[i][j][r] = 0.f;

    const int lr = tid >> 3;          // 0..31
    const int lc = (tid & 7) * 8;     // halves, 16B units
    const uint32_t s0 = smem_u32(dynsmem);

    auto load_tile = [&](int kc, int s) {
        const __half* ag = Ab + kc * BKH;
        const __half* bg = Bb + kc * BKH;
        const uint32_t abase = s0 + s * STGB;
        const uint32_t bbase = abase + AWB;
        #pragma unroll
        for (int i = 0; i < 4; i++) {
            const int r = lr + i * 32;
            cp_async16(abase + r * (KSH * 2) + lc * 2, ag + (size_t)r * K + lc);
        }
        #pragma unroll
        for (int i = 0; i < 8; i++) {
            const int r = lr + i * 32;
            cp_async16(bbase + r * (KSH * 2) + lc * 2, bg + (size_t)r * K + lc);
        }
        CP_COMMIT();
    };

    const int NCH = K / BKH;   // 16
    load_tile(0, 0);
    int buf = 0;

    for (int kc = 0; kc < NCH; kc++) {
        if (kc + 1 < NCH) {
            load_tile(kc + 1, buf ^ 1);
            CP_WAIT(1);
        } else {
            CP_WAIT(0);
        }
        __syncthreads();

        const uint32_t Ac = s0 + buf * STGB;
        const uint32_t Bc = Ac + AWB;

        #pragma unroll
        for (int ks = 0; ks < 4; ks++) {
            const int kb = ks * 16;
            uint32_t af[4][4], bf[8][2];
            const uint32_t aa = Ac + ((wm * 64 + al_row) * KSH + kb + al_col) * 2;
            #pragma unroll
            for (int i = 0; i < 4; i++)
                ldsm_x4(af[i][0], af[i][1], af[i][2], af[i][3],
                        aa + i * (16 * KSH * 2));
            const uint32_t ba = Bc + ((wn * 64 + bl_row) * KSH + kb + bl_col) * 2;
            #pragma unroll
            for (int jp = 0; jp < 4; jp++)
                ldsm_x4(bf[2 * jp][0], bf[2 * jp][1],
                        bf[2 * jp + 1][0], bf[2 * jp + 1][1],
                        ba + jp * (16 * KSH * 2));
            #pragma unroll
            for (int i = 0; i < 4; i++)
                #pragma unroll
                for (int j = 0; j < 8; j++)
                    mma_f16(acc[i][j], af[i], bf[j]);
        }
        __syncthreads();
        buf ^= 1;
    }

    #pragma unroll
    for (int i = 0; i < 4; i++) {
        #pragma unroll
        for (int j = 0; j < 8; j++) {
            const int m = row0 + wm * 64 + i * 16 + g;
            const int n = col0 + wn * 64 + j * 8 + 2 * t;
            if (MODE == 2) {
                float* C = (float*)Cv;
                *(float2*)&C[(size_t)m * N + n]       = make_float2(acc[i][j][0], acc[i][j][1]);
                *(float2*)&C[(size_t)(m + 8) * N + n] = make_float2(acc[i][j][2], acc[i][j][3]);
            } else if (MODE == 1) {
                __half* C = (__half*)Cv;
                C[(size_t)n * M + m]           = __float2half_rn(acc[i][j][0]);
                C[(size_t)(n + 1) * M + m]     = __float2half_rn(acc[i][j][1]);
                C[(size_t)n * M + m + 8]       = __float2half_rn(acc[i][j][2]);
                C[(size_t)(n + 1) * M + m + 8] = __float2half_rn(acc[i][j][3]);
            } else {
                __half* C = (__half*)Cv;
                *(uint32_t*)&C[(size_t)m * N + n]       = pack_h2(acc[i][j][0], acc[i][j][1]);
                *(uint32_t*)&C[(size_t)(m + 8) * N + n] = pack_h2(acc[i][j][2], acc[i][j][3]);
            }
        }
    }
}

// ---------------------------------------------------------------------------
// FP16 tensor-core causal flash attention v8.
// Structure = proven v7 (64q/CTA, 4 warps x 16q, Q in regs exp2-scaled,
// K 2-stage cp.async, V(transposed) single-buffered, 3 CTAs/SM) but all
// operands fp16 with m16n8k16: half the MMAs and fragment loads, no cvt.
// Smem (halves, rows padded to 72 = 144B): K[2][64][72], Vt[64][72],
// P[64][72] = 36.9KB.
// ---------------------------------------------------------------------------
#define KSTH 72
#define KT  64
#define QT  64
#define KSTGB (KT * KSTH * 2)            // 9216 B per K stage
#define AOFF_V (2 * KSTGB)               // 18432
#define AOFF_P (AOFF_V + KT * KSTH * 2)  // 27648
#define ASMEMH (AOFF_P + QT * KSTH * 2)  // 36864 B

__global__ void __launch_bounds__(128, 3) attn_tc(const __half* __restrict__ qg,
                                                  const __half* __restrict__ kg,
                                                  const __half* __restrict__ vtg,
                                                  __half* __restrict__ og)
{
    const int bh = blockIdx.y;
    const int b  = bh >> 4;
    const int h  = bh & 15;
    const int q0 = (gridDim.x - 1 - blockIdx.x) * QT;   // longest CTAs first
    const int tid = threadIdx.x;
    const int w = tid >> 5, lane = tid & 31;
    const int g = lane >> 2, t = lane & 3;

    const int al_row = ((lane >> 3) & 1) * 8 + (lane & 7);
    const int al_col = ((lane >> 4) & 1) * 8;
    const int bl_row = ((lane >> 4) & 1) * 8 + (lane & 7);
    const int bl_col = ((lane >> 3) & 1) * 8;

    const __half* kbase  = kg + ((size_t)(b * CS)) * CD + h * CDK;
    const __half* vtbase = vtg + ((size_t)(h * CDK)) * CM + (size_t)b * CS;

    // Q fragments (fp16, pre-scaled by log2(e)/8 -> exp2-domain softmax)
    const float QSCALE = 0.125f * 1.4426950408889634f;
    const __half* qbase = qg + ((size_t)(b * CS + q0)) * CD + h * CDK;
    uint32_t qf[4][4];
    {
        const __half* qr0 = qbase + (size_t)(16 * w + g) * CD;
        const __half* qr1 = qbase + (size_t)(16 * w + g + 8) * CD;
        #pragma unroll
        for (int kc = 0; kc < 4; kc++) {
            #pragma unroll
            for (int half8 = 0; half8 < 2; half8++) {
                int c0 = 16 * kc + 8 * half8 + 2 * t;
                float2 f0 = __half22float2(*(const __half2*)(qr0 + c0));
                float2 f1 = __half22float2(*(const __half2*)(qr1 + c0));
                qf[kc][2 * half8]     = pack_h2(f0.x * QSCALE, f0.y * QSCALE);
                qf[kc][2 * half8 + 1] = pack_h2(f1.x * QSCALE, f1.y * QSCALE);
            }
        }
    }

    const uint32_t sb = smem_u32(dynsmem);
    const uint32_t vb0 = sb + AOFF_V;
    const uint32_t pb0 = sb + AOFF_P;
    __half* Ps = (__half*)(dynsmem + AOFF_P);

    auto load_K = [&](int kt_, int s) {
        const int k0 = kt_ * KT;
        const uint32_t kd = sb + s * KSTGB;
        #pragma unroll
        for (int i = 0; i < 4; i++) {
            int idx = tid + i * 128;
            int r = idx >> 3, c = idx & 7;
            cp_async16(kd + r * (KSTH * 2) + c * 16, kbase + (size_t)(k0 + r) * CD + c * 8);
        }
        CP_COMMIT();
    };
    auto load_V = [&](int kt_) {
        const int k0 = kt_ * KT;
        #pragma unroll
        for (int i = 0; i < 4; i++) {
            int idx = tid + i * 128;
            int r = idx >> 3, c = idx & 7;
            cp_async16(vb0 + r * (KSTH * 2) + c * 16, vtbase + (size_t)r * CM + k0 + c * 8);
        }
        CP_COMMIT();
    };

    float o[8][4];
    #pragma unroll
    for (int nt = 0; nt < 8; nt++)
        #pragma unroll
        for (int c = 0; c < 4; c++) o[nt][c] = 0.f;
    float mrow[2] = {-1e30f, -1e30f};
    float lrow[2] = {0.f, 0.f};

    const int ntiles = q0 / KT + 1;
    int buf = 0;
    load_K(0, 0);
    load_V(0);

    for (int kt = 0; kt < ntiles; kt++) {
        const int k0 = kt * KT;
        if (kt + 1 < ntiles) {
            load_K(kt + 1, buf ^ 1);
            CP_WAIT(1);            // K(kt) and V(kt) complete
        } else {
            CP_WAIT(0);
        }
        __syncthreads();

        if (k0 <= q0 + 16 * w + 15) {
            const uint32_t Kb = sb + buf * KSTGB;

            // S = Q * K^T (fp16, k16 steps)
            float s[8][4];
            #pragma unroll
            for (int nt = 0; nt < 8; nt++)
                #pragma unroll
                for (int c = 0; c < 4; c++) s[nt][c] = 0.f;

            #pragma unroll
            for (int kc = 0; kc < 4; kc++) {
                uint32_t bf[8][2];
                const uint32_t ka = Kb + (bl_row * KSTH + 16 * kc + bl_col) * 2;
                #pragma unroll
                for (int jp = 0; jp < 4; jp++)
                    ldsm_x4(bf[2 * jp][0], bf[2 * jp][1],
                            bf[2 * jp + 1][0], bf[2 * jp + 1][1],
                            ka + jp * (16 * KSTH * 2));
                #pragma unroll
                for (int nt = 0; nt < 8; nt++)
                    mma_f16(s[nt], qf[kc], bf[nt]);
            }

            // causal mask (diagonal tiles only; scale folded into Q)
            const bool needmask = (k0 + KT - 1) > (q0 + 16 * w);
            if (needmask) {
                #pragma unroll
                for (int nt = 0; nt < 8; nt++)
                    #pragma unroll
                    for (int c = 0; c < 4; c++) {
                        int key = k0 + 8 * nt + 2 * t + (c & 1);
                        int qr  = q0 + 16 * w + 8 * (c >> 1) + g;
                        if (key > qr) s[nt][c] = -1e30f;
                    }
            }

            // online softmax in exp2 domain
            #pragma unroll
            for (int p = 0; p < 2; p++) {
                float mx = -1e30f;
                #pragma unroll
                for (int nt = 0; nt < 8; nt++) {
                    mx = fmaxf(mx, s[nt][2 * p]);
                    mx = fmaxf(mx, s[nt][2 * p + 1]);
                }
                mx = fmaxf(mx, __shfl_xor_sync(0xffffffffu, mx, 1));
                mx = fmaxf(mx, __shfl_xor_sync(0xffffffffu, mx, 2));
                const float mnew = fmaxf(mrow[p], mx);
                const float corr = exp2f(mrow[p] - mnew);
                mrow[p] = mnew;
                float ls = 0.f;
                #pragma unroll
                for (int nt = 0; nt < 8; nt++) {
                    float p0 = exp2f(s[nt][2 * p]     - mnew);
                    float p1 = exp2f(s[nt][2 * p + 1] - mnew);
                    s[nt][2 * p]     = p0;
                    s[nt][2 * p + 1] = p1;
                    ls += p0 + p1;
                }
                #pragma unroll
                for (int nt = 0; nt < 8; nt++) {
                    o[nt][2 * p]     *= corr;
                    o[nt][2 * p + 1] *= corr;
                }
                lrow[p] = lrow[p] * corr + ls;
            }

            // P -> smem fp16 (C-frag -> A-frag layout)
            #pragma unroll
            for (int p = 0; p < 2; p++) {
                const int row = 16 * w + 8 * p + g;
                #pragma unroll
                for (int nt = 0; nt < 8; nt++)
                    *(uint32_t*)&Ps[row * KSTH + 8 * nt + 2 * t] =
                        pack_h2(s[nt][2 * p], s[nt][2 * p + 1]);
            }
            __syncwarp();

            // O += P * V  (P ldmatrix A-pattern, Vt ldmatrix B-pattern)
            #pragma unroll
            for (int kc = 0; kc < 4; kc++) {
                uint32_t af[4];
                ldsm_x4(af[0], af[1], af[2], af[3],
                        pb0 + ((16 * w + al_row) * KSTH + 16 * kc + al_col) * 2);
                uint32_t bf[8][2];
                const uint32_t va = vb0 + (bl_row * KSTH + 16 * kc + bl_col) * 2;
                #pragma unroll
                for (int jp = 0; jp < 4; jp++)
                    ldsm_x4(bf[2 * jp][0], bf[2 * jp][1],
                            bf[2 * jp + 1][0], bf[2 * jp + 1][1],
                            va + jp * (16 * KSTH * 2));
                #pragma unroll
                for (int nt = 0; nt < 8; nt++)
                    mma_f16(o[nt], af, bf[nt]);
            }
        }
        __syncthreads();           // all warps done with V(kt)
        if (kt + 1 < ntiles) load_V(kt + 1);
        buf ^= 1;
    }

    // finalize
    float inv[2];
    #pragma unroll
    for (int p = 0; p < 2; p++) {
        float lr = lrow[p];
        lr += __shfl_xor_sync(0xffffffffu, lr, 1);
        lr += __shfl_xor_sync(0xffffffffu, lr, 2);
        inv[p] = 1.f / lr;
    }

    __half* obase = og + ((size_t)(b * CS + q0)) * CD + h * CDK;
    #pragma unroll
    for (int nt = 0; nt < 8; nt++) {
        const int r0 = 16 * w + g;
        *(uint32_t*)(obase + (size_t)r0 * CD + 8 * nt + 2 * t) =
            pack_h2(o[nt][0] * inv[0], o[nt][1] * inv[0]);
        *(uint32_t*)(obase + (size_t)(r0 + 8) * CD + 8 * nt + 2 * t) =
            pack_h2(o[nt][2] * inv[1], o[nt][3] * inv[1]);
    }
}

// ---------------------------------------------------------------------------
// Launch. Inputs: Q, K, V, mask(ignored), w_q, w_k, w_v, w_o. Out: [B,S,D] f32
// ---------------------------------------------------------------------------
extern "C" void kernel_launch(void* const* d_in, const int* in_sizes, int n_in,
                              void* d_out, int out_size)
{
    const float* Q  = (const float*)d_in[0];
    const float* K  = (const float*)d_in[1];
    const float* V  = (const float*)d_in[2];
    const float* wq = (const float*)d_in[4];
    const float* wk = (const float*)d_in[5];
    const float* wv = (const float*)d_in[6];
    const float* wo = (const float*)d_in[7];
    float* out = (float*)d_out;

    __half *hiq, *hik, *hiv, *hwq, *hwk, *hwv, *hwo, *hq, *hk, *hvt, *hao;
    cudaGetSymbolAddress((void**)&hiq, h_in_q);
    cudaGetSymbolAddress((void**)&hik, h_in_k);
    cudaGetSymbolAddress((void**)&hiv, h_in_v);
    cudaGetSymbolAddress((void**)&hwq, h_wq);
    cudaGetSymbolAddress((void**)&hwk, h_wk);
    cudaGetSymbolAddress((void**)&hwv, h_wv);
    cudaGetSymbolAddress((void**)&hwo, h_wo);
    cudaGetSymbolAddress((void**)&hq,  h_q);
    cudaGetSymbolAddress((void**)&hk,  h_k);
    cudaGetSymbolAddress((void**)&hvt, h_vt);
    cudaGetSymbolAddress((void**)&hao, h_ao);

    cudaFuncSetAttribute(gemm_h<0>, cudaFuncAttributeMaxDynamicSharedMemorySize, GSMEMH);
    cudaFuncSetAttribute(gemm_h<1>, cudaFuncAttributeMaxDynamicSharedMemorySize, GSMEMH);
    cudaFuncSetAttribute(gemm_h<2>, cudaFuncAttributeMaxDynamicSharedMemorySize, GSMEMH);
    cudaFuncSetAttribute(attn_tc, cudaFuncAttributeMaxDynamicSharedMemorySize, ASMEMH);

    const int NT4 = CB * CS * CD / 4;   // 1048576
    const int NW4 = CD * CD / 4;        // 262144
    cvt16<<<NT4 / 256, 256>>>(Q, hiq, NT4);
    cvt16<<<NT4 / 256, 256>>>(K, hik, NT4);
    cvt16<<<NT4 / 256, 256>>>(V, hiv, NT4);
    cvt16<<<NW4 / 256, 256>>>(wq, hwq, NW4);
    cvt16<<<NW4 / 256, 256>>>(wk, hwk, NW4);
    cvt16<<<NW4 / 256, 256>>>(wv, hwv, NW4);
    cvt16<<<NW4 / 256, 256>>>(wo, hwo, NW4);

    dim3 gg(CD / BN, CM / BM);   // (4, 32) = 128 CTAs, single wave
    gemm_h<0><<<gg, 256, GSMEMH>>>(hiq, hwq, hq,  CM, CD, CD);
    gemm_h<0><<<gg, 256, GSMEMH>>>(hik, hwk, hk,  CM, CD, CD);
    gemm_h<1><<<gg, 256, GSMEMH>>>(hiv, hwv, hvt, CM, CD, CD);   // writes Vt

    attn_tc<<<dim3(CS / QT, CB * CH), 128, ASMEMH>>>(hq, hk, hvt, hao);

    gemm_h<2><<<gg, 256, GSMEMH>>>(hao, hwo, out, CM, CD, CD);
}